// round 1
// baseline (speedup 1.0000x reference)
#include <cuda_runtime.h>
#include <cstdint>

#define D 128
#define MAX_N 100000
#define MAX_E 1600000
#define TILE_M 64
#define XS_STRIDE 132   // padded to kill bank conflicts on Xs[r][k] (r differs by 4 within warp)

// ---------------- scratch (static device globals; no allocation) ----------------
__device__ float g_h[(size_t)MAX_N * D];      // x @ W
__device__ int   g_cnt[MAX_N + 1];
__device__ int   g_incl[MAX_N + 32];
__device__ int   g_bsum[128];
__device__ int   g_boff[128];
__device__ int   g_rowstart[MAX_N + 1];
__device__ int   g_cursor[MAX_N + 1];
__device__ int   g_scol[MAX_E];
__device__ float g_sval[MAX_E];

// ---------------- GEMM: h = x @ W, fp32 with packed f32x2 FMAs ----------------
// block: 256 threads, TILE_M=64 rows x 128 cols.
// thread (tr,tc): rows r0..r0+3, cols [tc*4..tc*4+3] and [64+tc*4..64+tc*4+3]
// accumulators kept as packed f32x2 (cols paired), W read from smem as ulonglong2
// (already pair-packed in memory), x broadcast-packed via mov.b64 {x,x}.
__global__ void __launch_bounds__(256, 2)
gemm_kernel(const float* __restrict__ x, const float* __restrict__ w, int n)
{
    extern __shared__ float smem[];
    float* Ws = smem;                 // 128*128
    float* Xs = smem + D * D;         // TILE_M * XS_STRIDE

    const int tid = threadIdx.x;
    const int m0  = blockIdx.x * TILE_M;

    // load full W (16384 floats = 4096 float4, 16 per thread), coalesced
    {
        const float4* wsrc = (const float4*)w;
        float4* wdst = (float4*)Ws;
        #pragma unroll
        for (int i = 0; i < 16; i++) wdst[tid + 256 * i] = wsrc[tid + 256 * i];
    }
    // load x tile (64 rows x 128 = 2048 float4, 8 per thread) into padded smem
    {
        const float4* xsrc = (const float4*)x;
        #pragma unroll
        for (int i = 0; i < 8; i++) {
            int idx = tid + 256 * i;          // float4 index within unpadded tile
            int r   = idx >> 5;               // 32 float4 per row
            int c4  = idx & 31;
            int gr  = m0 + r;
            float4 v = (gr < n) ? xsrc[(size_t)gr * 32 + c4] : make_float4(0.f, 0.f, 0.f, 0.f);
            *(float4*)(Xs + r * XS_STRIDE + c4 * 4) = v;
        }
    }
    __syncthreads();

    const int tc = tid & 15;   // column group
    const int tr = tid >> 4;   // row group
    const int r0 = tr * 4;

    unsigned long long acc[4][4];
    #pragma unroll
    for (int i = 0; i < 4; i++)
        #pragma unroll
        for (int j = 0; j < 4; j++) acc[i][j] = 0ull;

    #pragma unroll 4
    for (int k = 0; k < D; k++) {
        // W row k, pair-packed: cols [tc*4..+3] and [64+tc*4..+3]
        const ulonglong2 w0 = *(const ulonglong2*)(Ws + k * D + tc * 4);
        const ulonglong2 w1 = *(const ulonglong2*)(Ws + k * D + 64 + tc * 4);
        unsigned long long wp0 = w0.x, wp1 = w0.y, wp2 = w1.x, wp3 = w1.y;
        #pragma unroll
        for (int i = 0; i < 4; i++) {
            float xv = Xs[(r0 + i) * XS_STRIDE + k];
            unsigned long long xp;
            asm("mov.b64 %0, {%1, %1};" : "=l"(xp) : "f"(xv));
            asm("fma.rn.f32x2 %0, %1, %2, %0;" : "+l"(acc[i][0]) : "l"(xp), "l"(wp0));
            asm("fma.rn.f32x2 %0, %1, %2, %0;" : "+l"(acc[i][1]) : "l"(xp), "l"(wp1));
            asm("fma.rn.f32x2 %0, %1, %2, %0;" : "+l"(acc[i][2]) : "l"(xp), "l"(wp2));
            asm("fma.rn.f32x2 %0, %1, %2, %0;" : "+l"(acc[i][3]) : "l"(xp), "l"(wp3));
        }
    }

    #pragma unroll
    for (int i = 0; i < 4; i++) {
        int gr = m0 + r0 + i;
        if (gr < n) {
            float* hrow = g_h + (size_t)gr * D;
            ulonglong2 s01; s01.x = acc[i][0]; s01.y = acc[i][1];
            ulonglong2 s23; s23.x = acc[i][2]; s23.y = acc[i][3];
            *(ulonglong2*)(hrow + tc * 4)      = s01;
            *(ulonglong2*)(hrow + 64 + tc * 4) = s23;
        }
    }
}

// ---------------- CSR build ----------------
__global__ void zero_cnt_kernel(int n)
{
    int i = blockIdx.x * blockDim.x + threadIdx.x;
    if (i <= n) g_cnt[i] = 0;
}

__global__ void hist_kernel(const int* __restrict__ rows, int e)
{
    int i = blockIdx.x * blockDim.x + threadIdx.x;
    if (i < e) atomicAdd(&g_cnt[rows[i]], 1);
}

// block-level inclusive scan (Hillis-Steele), 1024 threads/block
__global__ void scan1_kernel(int n)
{
    __shared__ int s[1024];
    int i = blockIdx.x * 1024 + threadIdx.x;
    int v = (i < n) ? g_cnt[i] : 0;
    s[threadIdx.x] = v;
    __syncthreads();
    #pragma unroll
    for (int off = 1; off < 1024; off <<= 1) {
        int t = (threadIdx.x >= off) ? s[threadIdx.x - off] : 0;
        __syncthreads();
        s[threadIdx.x] += t;
        __syncthreads();
    }
    if (i < n) g_incl[i] = s[threadIdx.x];
    if (threadIdx.x == 1023) g_bsum[blockIdx.x] = s[1023];
}

// single-block scan of block sums -> exclusive block offsets (nb <= 128)
__global__ void scan2_kernel(int nb)
{
    __shared__ int s[128];
    int v = (threadIdx.x < nb) ? g_bsum[threadIdx.x] : 0;
    s[threadIdx.x] = v;
    __syncthreads();
    #pragma unroll
    for (int off = 1; off < 128; off <<= 1) {
        int t = (threadIdx.x >= off) ? s[threadIdx.x - off] : 0;
        __syncthreads();
        s[threadIdx.x] += t;
        __syncthreads();
    }
    g_boff[threadIdx.x] = s[threadIdx.x] - v;   // exclusive
}

__global__ void scan3_kernel(int n)
{
    int i = blockIdx.x * 1024 + threadIdx.x;
    if (i < n) {
        int v = g_incl[i] + g_boff[blockIdx.x];
        g_rowstart[i + 1] = v;
        g_cursor[i + 1]   = v;
        if (i == 0) { g_rowstart[0] = 0; g_cursor[0] = 0; }
    }
}

__global__ void fill_kernel(const int* __restrict__ rows, const int* __restrict__ cols,
                            const float* __restrict__ vals, int e)
{
    int i = blockIdx.x * blockDim.x + threadIdx.x;
    if (i < e) {
        int r = rows[i];
        int p = atomicAdd(&g_cursor[r], 1);
        g_scol[p] = cols[i];
        g_sval[p] = vals[i];
    }
}

// ---------------- aggregation: one warp per row, no atomics ----------------
__global__ void agg_kernel(float* __restrict__ out, int n)
{
    int gw   = (blockIdx.x * blockDim.x + threadIdx.x) >> 5;
    int lane = threadIdx.x & 31;
    if (gw >= n) return;

    int s = g_rowstart[gw];
    int e = g_rowstart[gw + 1];

    float a0 = 0.f, a1 = 0.f, a2 = 0.f, a3 = 0.f;
    const float* __restrict__ h = g_h;
    for (int p = s; p < e; p++) {
        int   c = __ldg(&g_scol[p]);
        float v = __ldg(&g_sval[p]);
        float4 hv = *(const float4*)(h + (size_t)c * D + lane * 4);
        a0 += v * hv.x;
        a1 += v * hv.y;
        a2 += v * hv.z;
        a3 += v * hv.w;
    }
    float4 o;
    o.x = fmaxf(a0, 0.f);
    o.y = fmaxf(a1, 0.f);
    o.z = fmaxf(a2, 0.f);
    o.w = fmaxf(a3, 0.f);
    *(float4*)(out + (size_t)gw * D + lane * 4) = o;
}

// ---------------- launch ----------------
extern "C" void kernel_launch(void* const* d_in, const int* in_sizes, int n_in,
                              void* d_out, int out_size)
{
    const float* x  = (const float*)d_in[0];
    const float* w  = (const float*)d_in[1];
    const float* ev = (const float*)d_in[2];
    const int*   er = (const int*)d_in[3];
    const int*   ec = (const int*)d_in[4];
    float* out = (float*)d_out;

    const int n = in_sizes[0] / D;      // 100000
    const int e = in_sizes[2];          // 1600000

    // CSR build
    zero_cnt_kernel<<<(n + 256) / 256, 256>>>(n);
    hist_kernel<<<(e + 255) / 256, 256>>>(er, e);
    int nb = (n + 1023) / 1024;
    scan1_kernel<<<nb, 1024>>>(n);
    scan2_kernel<<<1, 128>>>(nb);
    scan3_kernel<<<nb, 1024>>>(n);
    fill_kernel<<<(e + 255) / 256, 256>>>(er, ec, ev, e);

    // GEMM (right before aggregation so h is L2-resident for the gathers)
    const int smem_bytes = (D * D + TILE_M * XS_STRIDE) * (int)sizeof(float);
    cudaFuncSetAttribute(gemm_kernel, cudaFuncAttributeMaxDynamicSharedMemorySize, smem_bytes);
    gemm_kernel<<<(n + TILE_M - 1) / TILE_M, 256, smem_bytes>>>(x, w, n);

    // aggregation: one warp per row
    int total_threads = n * 32;
    agg_kernel<<<(total_threads + 255) / 256, 256>>>(out, n);
}

// round 3
// speedup vs baseline: 1.3375x; 1.3375x over previous
#include <cuda_runtime.h>
#include <cuda_bf16.h>
#include <cuda_fp16.h>
#include <cstdint>

#define D 128
#define MAX_N 100000
#define MAX_E 1600000

// ---------------- scratch (static device globals; no allocation) ----------------
__device__ __align__(16) __half g_h16[(size_t)MAX_N * D];   // x @ W, fp16
__device__ int   g_cnt[MAX_N + 1];
__device__ int   g_rowstart[MAX_N + 1];
__device__ int   g_cursor[MAX_N + 1];
__device__ int   g_scol[MAX_E];
__device__ float g_sval[MAX_E];
__device__ __align__(16) __nv_bfloat16 g_wt_hi[D * D];      // W^T split, [n][k]
__device__ __align__(16) __nv_bfloat16 g_wt_lo[D * D];
__device__ int   g_blk_aggr[128];
__device__ int   g_blk_flag[128];

// =============== prep: W split + zero cnt + reset scan flags ===============
__global__ void prep_kernel(const float* __restrict__ w, int n)
{
    int i = blockIdx.x * blockDim.x + threadIdx.x;
    if (i < D * D) {
        int k = i >> 7, nn = i & 127;
        float v = w[i];                               // w[k*128+n]
        __nv_bfloat16 hi = __float2bfloat16_rn(v);
        float lo = v - __bfloat162float(hi);
        g_wt_hi[nn * D + k] = hi;
        g_wt_lo[nn * D + k] = __float2bfloat16_rn(lo);
    }
    if (i <= n) g_cnt[i] = 0;
    if (i < 128) { g_blk_flag[i] = 0; g_blk_aggr[i] = 0; }
}

// ---------------- CSR build ----------------
__global__ void hist_kernel(const int* __restrict__ rows, int e)
{
    int i = blockIdx.x * blockDim.x + threadIdx.x;
    if (i < e) atomicAdd(&g_cnt[rows[i]], 1);
}

// single-pass scan with decoupled lookback; grid (<=128 blocks) all resident in wave 1
__global__ void scan_kernel(int n)
{
    __shared__ int s[1024];
    __shared__ int pref;
    const int b = blockIdx.x;
    const int tid = threadIdx.x;
    int i = b * 1024 + tid;
    int v = (i < n) ? g_cnt[i] : 0;
    s[tid] = v;
    if (tid == 0) pref = 0;
    __syncthreads();
    #pragma unroll
    for (int off = 1; off < 1024; off <<= 1) {
        int t = (tid >= off) ? s[tid - off] : 0;
        __syncthreads();
        s[tid] += t;
        __syncthreads();
    }
    if (tid == 0) {
        g_blk_aggr[b] = s[1023];
        __threadfence();
        atomicExch(&g_blk_flag[b], 1);
    }
    if (tid < b) {                       // parallel lookback (all blocks resident)
        while (atomicAdd(&g_blk_flag[tid], 0) == 0) { }
        int va = g_blk_aggr[tid];
        atomicAdd(&pref, va);
    }
    __syncthreads();
    if (i < n) {
        int incl = s[tid] + pref;
        g_rowstart[i + 1] = incl;
        g_cursor[i + 1]   = incl;
        if (i == 0) { g_rowstart[0] = 0; g_cursor[0] = 0; }
    }
}

__global__ void fill_kernel(const int* __restrict__ rows, const int* __restrict__ cols,
                            const float* __restrict__ vals, int e)
{
    int i = blockIdx.x * blockDim.x + threadIdx.x;
    if (i < e) {
        int r = rows[i];
        int p = atomicAdd(&g_cursor[r], 1);
        g_scol[p] = cols[i];
        g_sval[p] = vals[i];
    }
}

// =============== GEMM: h = x @ W via mma.sync bf16, 3-product split ===============
// CTA: 256 threads (8 warps), tile 128 rows x 128 cols, K=128 fully in smem.
// warp (wm = wid&3, wn = wid>>2): rows [wm*32,+32), cols [wn*64,+64).
// smem tiles stride 136 bf16 (272B) -> all fragment LDS conflict-free:
// bank = (68*g + q) mod 32 = (4g+q) mod 32, distinct over g=0..7,q=0..3.
#define AS 136
#define SM_AHI 0
#define SM_ALO (128 * AS * 2)
#define SM_BHI (2 * 128 * AS * 2)
#define SM_BLO (3 * 128 * AS * 2)
#define SM_TOT (4 * 128 * AS * 2)

__device__ __forceinline__ void mma_bf16(float* c, const uint32_t* a, uint32_t b0, uint32_t b1)
{
    asm volatile(
        "mma.sync.aligned.m16n8k16.row.col.f32.bf16.bf16.f32 "
        "{%0,%1,%2,%3}, {%4,%5,%6,%7}, {%8,%9}, {%0,%1,%2,%3};"
        : "+f"(c[0]), "+f"(c[1]), "+f"(c[2]), "+f"(c[3])
        : "r"(a[0]), "r"(a[1]), "r"(a[2]), "r"(a[3]), "r"(b0), "r"(b1));
}

__global__ void __launch_bounds__(256, 1)
gemm_tc_kernel(const float* __restrict__ x, int n)
{
    extern __shared__ char smem[];
    __nv_bfloat16* sAhi = (__nv_bfloat16*)(smem + SM_AHI);
    __nv_bfloat16* sAlo = (__nv_bfloat16*)(smem + SM_ALO);
    __nv_bfloat16* sBhi = (__nv_bfloat16*)(smem + SM_BHI);
    __nv_bfloat16* sBlo = (__nv_bfloat16*)(smem + SM_BLO);

    const int tid = threadIdx.x;
    const int m0  = blockIdx.x * 128;

    // B: 128x128 bf16 x2, 16B vector copies (row stride 272B is 16B-multiple)
    #pragma unroll
    for (int t = 0; t < 8; t++) {
        int i = tid + 256 * t;                  // uint4 index, 2048 total
        int row = i >> 4, kc = (i & 15) * 8;
        uint4 vh = *(const uint4*)(g_wt_hi + row * D + kc);
        uint4 vl = *(const uint4*)(g_wt_lo + row * D + kc);
        *(uint4*)(sBhi + row * AS + kc) = vh;
        *(uint4*)(sBlo + row * AS + kc) = vl;
    }
    // A: x tile 128x128 f32, split -> bf16 hi/lo
    #pragma unroll
    for (int t = 0; t < 16; t++) {
        int i = tid + 256 * t;                  // float4 index, 4096 total
        int row = i >> 5, c4 = (i & 31) * 4;
        int gm = m0 + row;
        float4 v = (gm < n) ? *(const float4*)(x + (size_t)gm * D + c4)
                            : make_float4(0.f, 0.f, 0.f, 0.f);
        __nv_bfloat16 h0 = __float2bfloat16_rn(v.x), h1 = __float2bfloat16_rn(v.y);
        __nv_bfloat16 h2 = __float2bfloat16_rn(v.z), h3 = __float2bfloat16_rn(v.w);
        __nv_bfloat16 l0 = __float2bfloat16_rn(v.x - __bfloat162float(h0));
        __nv_bfloat16 l1 = __float2bfloat16_rn(v.y - __bfloat162float(h1));
        __nv_bfloat16 l2 = __float2bfloat16_rn(v.z - __bfloat162float(h2));
        __nv_bfloat16 l3 = __float2bfloat16_rn(v.w - __bfloat162float(h3));
        uint32_t hp0 = ((uint32_t)__bfloat16_as_ushort(h1) << 16) | __bfloat16_as_ushort(h0);
        uint32_t hp1 = ((uint32_t)__bfloat16_as_ushort(h3) << 16) | __bfloat16_as_ushort(h2);
        uint32_t lp0 = ((uint32_t)__bfloat16_as_ushort(l1) << 16) | __bfloat16_as_ushort(l0);
        uint32_t lp1 = ((uint32_t)__bfloat16_as_ushort(l3) << 16) | __bfloat16_as_ushort(l2);
        uint2 hq; hq.x = hp0; hq.y = hp1;
        uint2 lq; lq.x = lp0; lq.y = lp1;
        *(uint2*)(sAhi + row * AS + c4) = hq;
        *(uint2*)(sAlo + row * AS + c4) = lq;
    }
    __syncthreads();

    const int wid  = tid >> 5;
    const int lane = tid & 31;
    const int g = lane >> 2, q = lane & 3;
    const int m_base = (wid & 3) * 32;
    const int n_base = (wid >> 2) * 64;

    float acc[2][8][4];
    #pragma unroll
    for (int mi = 0; mi < 2; mi++)
        #pragma unroll
        for (int ni = 0; ni < 8; ni++)
            #pragma unroll
            for (int r = 0; r < 4; r++) acc[mi][ni][r] = 0.f;

    #pragma unroll
    for (int prod = 0; prod < 3; prod++) {
        const __nv_bfloat16* A = (prod == 2) ? sAlo : sAhi;
        const __nv_bfloat16* B = (prod == 1) ? sBlo : sBhi;
        #pragma unroll
        for (int ks = 0; ks < 8; ks++) {
            const int k0 = ks * 16;
            uint32_t a[2][4];
            #pragma unroll
            for (int mi = 0; mi < 2; mi++) {
                const int r0 = m_base + mi * 16;
                a[mi][0] = *(const uint32_t*)(A + (r0 + g)     * AS + k0     + q * 2);
                a[mi][1] = *(const uint32_t*)(A + (r0 + g + 8) * AS + k0     + q * 2);
                a[mi][2] = *(const uint32_t*)(A + (r0 + g)     * AS + k0 + 8 + q * 2);
                a[mi][3] = *(const uint32_t*)(A + (r0 + g + 8) * AS + k0 + 8 + q * 2);
            }
            #pragma unroll
            for (int ni = 0; ni < 8; ni++) {
                const int nr = n_base + ni * 8 + g;
                uint32_t b0 = *(const uint32_t*)(B + nr * AS + k0     + q * 2);
                uint32_t b1 = *(const uint32_t*)(B + nr * AS + k0 + 8 + q * 2);
                mma_bf16(acc[0][ni], a[0], b0, b1);
                mma_bf16(acc[1][ni], a[1], b0, b1);
            }
        }
    }

    // epilogue: f32 acc -> fp16 h. c0/c1: row g, cols q*2,q*2+1; c2/c3: row g+8.
    #pragma unroll
    for (int mi = 0; mi < 2; mi++) {
        const int r0 = m0 + m_base + mi * 16;
        #pragma unroll
        for (int ni = 0; ni < 8; ni++) {
            const int col = n_base + ni * 8 + q * 2;
            int ra = r0 + g, rb = r0 + g + 8;
            if (ra < n)
                *(__half2*)(g_h16 + (size_t)ra * D + col) =
                    __floats2half2_rn(acc[mi][ni][0], acc[mi][ni][1]);
            if (rb < n)
                *(__half2*)(g_h16 + (size_t)rb * D + col) =
                    __floats2half2_rn(acc[mi][ni][2], acc[mi][ni][3]);
        }
    }
}

// ---------------- aggregation: one warp per row, fp16 h gathers, no atomics ----------------
__global__ void agg_kernel(float* __restrict__ out, int n)
{
    int gw   = (blockIdx.x * blockDim.x + threadIdx.x) >> 5;
    int lane = threadIdx.x & 31;
    if (gw >= n) return;

    int s = g_rowstart[gw];
    int e = g_rowstart[gw + 1];

    float a0 = 0.f, a1 = 0.f, a2 = 0.f, a3 = 0.f;
    const __half* __restrict__ h = g_h16;
    for (int p = s; p < e; p++) {
        int   c = __ldg(&g_scol[p]);
        float v = __ldg(&g_sval[p]);
        uint2 hv = *(const uint2*)(h + (size_t)c * D + lane * 4);
        float2 f0 = __half22float2(*(__half2*)&hv.x);
        float2 f1 = __half22float2(*(__half2*)&hv.y);
        a0 += v * f0.x;
        a1 += v * f0.y;
        a2 += v * f1.x;
        a3 += v * f1.y;
    }
    float4 o;
    o.x = fmaxf(a0, 0.f);
    o.y = fmaxf(a1, 0.f);
    o.z = fmaxf(a2, 0.f);
    o.w = fmaxf(a3, 0.f);
    *(float4*)(out + (size_t)gw * D + lane * 4) = o;
}

// ---------------- launch ----------------
extern "C" void kernel_launch(void* const* d_in, const int* in_sizes, int n_in,
                              void* d_out, int out_size)
{
    const float* x  = (const float*)d_in[0];
    const float* w  = (const float*)d_in[1];
    const float* ev = (const float*)d_in[2];
    const int*   er = (const int*)d_in[3];
    const int*   ec = (const int*)d_in[4];
    float* out = (float*)d_out;

    const int n = in_sizes[0] / D;      // 100000
    const int e = in_sizes[2];          // 1600000

    prep_kernel<<<(n + 256) / 256, 256>>>(w, n);
    hist_kernel<<<(e + 255) / 256, 256>>>(er, e);
    int nb = (n + 1023) / 1024;         // 98 <= 128, single-wave lookback
    scan_kernel<<<nb, 1024>>>(n);
    fill_kernel<<<(e + 255) / 256, 256>>>(er, ec, ev, e);

    cudaFuncSetAttribute(gemm_tc_kernel, cudaFuncAttributeMaxDynamicSharedMemorySize, SM_TOT);
    gemm_tc_kernel<<<(n + 127) / 128, 256, SM_TOT>>>(x, n);

    int total_threads = n * 32;
    agg_kernel<<<(total_threads + 255) / 256, 256>>>(out, n);
}